// round 1
// baseline (speedup 1.0000x reference)
#include <cuda_runtime.h>
#include <math.h>

// Problem constants (fixed by the reference)
#define POOL   100
#define NTASKS 10
#define PLEN   8
#define EMBD   768
#define BATCH  512
#define ED4    (EMBD / 4)   // 192

// Scratch (allocation-free per harness rules)
__device__ float g_diag[POOL * EMBD];
__device__ float g_sim[BATCH * POOL];

// ---------------------------------------------------------------------------
// Kernel 0: diag[k,d] = sum_l e_p[k,l,d]^2   (POOL x EMBD, float4 vectorized)
// ---------------------------------------------------------------------------
__global__ void diag_kernel(const float* __restrict__ e_p) {
    int i = blockIdx.x * blockDim.x + threadIdx.x;   // over POOL*ED4
    if (i >= POOL * ED4) return;
    int k  = i / ED4;
    int d4 = i % ED4;
    const float4* ep4 = (const float4*)e_p;
    float4 acc = make_float4(0.f, 0.f, 0.f, 0.f);
#pragma unroll
    for (int l = 0; l < PLEN; l++) {
        float4 v = ep4[((size_t)k * PLEN + l) * ED4 + d4];
        acc.x += v.x * v.x; acc.y += v.y * v.y;
        acc.z += v.z * v.z; acc.w += v.w * v.w;
    }
    ((float4*)g_diag)[i] = acc;
}

// ---------------------------------------------------------------------------
// Kernel 1: sim[b,k] — one warp per (b,k)
//   a = xq * ea;  s1 = Σ a^2 diag;  s2 = Σ a^2 diag^2;  s3 = Σ a^2
//   sim = s1 / (max(sqrt(s2),eps) * max(sqrt(s3),eps))
// ---------------------------------------------------------------------------
__global__ void sim_kernel(const float* __restrict__ x_querry,
                           const float* __restrict__ e_a,
                           const int*   __restrict__ task_id_p) {
    const int task_end = (*task_id_p + 1) * (POOL / NTASKS);
    int warp = (blockIdx.x * blockDim.x + threadIdx.x) >> 5;
    int lane = threadIdx.x & 31;
    int b = warp / POOL;
    int k = warp % POOL;
    if (b >= BATCH || k >= task_end) return;
    int row = POOL - task_end + k;

    const float4* xq4 = (const float4*)(x_querry + ((size_t)b * POOL + row) * EMBD);
    const float4* ea4 = (const float4*)(e_a + (size_t)k * EMBD);
    const float4* dg4 = (const float4*)(g_diag + (size_t)k * EMBD);

    float s1 = 0.f, s2 = 0.f, s3 = 0.f;
#pragma unroll
    for (int j = 0; j < ED4 / 32; j++) {   // 6 iterations
        int idx = lane + j * 32;
        float4 x = xq4[idx];
        float4 e = ea4[idx];
        float4 g = dg4[idx];
        float a, aa;
        a = x.x * e.x; aa = a * a; s3 += aa; s1 += aa * g.x; s2 += aa * g.x * g.x;
        a = x.y * e.y; aa = a * a; s3 += aa; s1 += aa * g.y; s2 += aa * g.y * g.y;
        a = x.z * e.z; aa = a * a; s3 += aa; s1 += aa * g.z; s2 += aa * g.z * g.z;
        a = x.w * e.w; aa = a * a; s3 += aa; s1 += aa * g.w; s2 += aa * g.w * g.w;
    }
#pragma unroll
    for (int o = 16; o > 0; o >>= 1) {
        s1 += __shfl_down_sync(0xFFFFFFFFu, s1, o);
        s2 += __shfl_down_sync(0xFFFFFFFFu, s2, o);
        s3 += __shfl_down_sync(0xFFFFFFFFu, s3, o);
    }
    if (lane == 0) {
        const float eps = 1e-12f;
        float n1 = fmaxf(sqrtf(s2), eps);
        float n2 = fmaxf(sqrtf(s3), eps);
        g_sim[(size_t)b * POOL + k] = s1 / (n1 * n2);
    }
}

// ---------------------------------------------------------------------------
// Kernel 2: int_pmt[b,l,d] = Σ_k sim[b,k] * e_p[k,l,d]
//   Written split: l<4 -> key region (offset 0), l>=4 -> value region.
//   One block per (b,l); 192 threads, one float4 each.
// ---------------------------------------------------------------------------
__global__ void pmt_kernel(const float* __restrict__ e_p,
                           const int*   __restrict__ task_id_p,
                           float* __restrict__ out) {
    const int task_end = (*task_id_p + 1) * (POOL / NTASKS);
    int b = blockIdx.x / PLEN;
    int l = blockIdx.x % PLEN;
    int d4 = threadIdx.x;                  // 0..191

    const float4* ep4  = (const float4*)e_p;
    const float*  simb = g_sim + (size_t)b * POOL;

    float4 acc = make_float4(0.f, 0.f, 0.f, 0.f);
    for (int k = 0; k < task_end; k++) {
        float s = simb[k];
        float4 v = ep4[((size_t)k * PLEN + l) * ED4 + d4];
        acc.x += s * v.x; acc.y += s * v.y;
        acc.z += s * v.z; acc.w += s * v.w;
    }

    const size_t KEY4 = (size_t)BATCH * (PLEN / 2) * ED4;  // key region in float4s
    float4* o4;
    if (l < PLEN / 2) {
        o4 = (float4*)out + ((size_t)b * (PLEN / 2) + l) * ED4;
    } else {
        o4 = (float4*)out + KEY4 + ((size_t)b * (PLEN / 2) + (l - PLEN / 2)) * ED4;
    }
    o4[d4] = acc;
}

// ---------------------------------------------------------------------------
// Launch
// Inputs (metadata order): x_querry, x_block, e_a, e_p, idx, task_id
// Output: [int_e_key (512*4*768) | int_e_value (512*4*768) | x_block (512*197*768)] fp32
// ---------------------------------------------------------------------------
extern "C" void kernel_launch(void* const* d_in, const int* in_sizes, int n_in,
                              void* d_out, int out_size) {
    const float* x_querry = (const float*)d_in[0];
    const float* x_block  = (const float*)d_in[1];
    const float* e_a      = (const float*)d_in[2];
    const float* e_p      = (const float*)d_in[3];
    const int*   task_id  = (const int*)d_in[5];
    float* out = (float*)d_out;

    // Big pass-through copy first (dominant work — driver copy path)
    const size_t XB_OFF   = (size_t)BATCH * PLEN * EMBD;            // 3,145,728 floats
    const size_t XB_BYTES = (size_t)in_sizes[1] * sizeof(float);    // 512*197*768*4
    cudaMemcpyAsync(out + XB_OFF, x_block, XB_BYTES, cudaMemcpyDeviceToDevice);

    // diag: POOL*ED4 = 19200 threads
    {
        int n = POOL * ED4;
        diag_kernel<<<(n + 255) / 256, 256>>>(e_p);
    }
    // sim: BATCH*POOL warps
    {
        long long threads = (long long)BATCH * POOL * 32;
        sim_kernel<<<(int)((threads + 255) / 256), 256>>>(x_querry, e_a, task_id);
    }
    // pmt: one block per (b,l)
    pmt_kernel<<<BATCH * PLEN, ED4>>>(e_p, task_id, out);
}

// round 2
// speedup vs baseline: 1.0801x; 1.0801x over previous
#include <cuda_runtime.h>
#include <math.h>

// Problem constants (fixed by the reference)
#define POOL   100
#define NTASKS 10
#define PLEN   8
#define EMBD   768
#define BATCH  512
#define ED4    (EMBD / 4)   // 192

#define PMT_BLOCKS  BATCH            // 512 blocks doing the einsum
#define COPY_BLOCKS 2560             // blocks doing the streaming copy
#define BG          8                // batch rows per sim block (one warp each)

// Scratch (allocation-free per harness rules)
__device__ float g_sim[BATCH * POOL];

// ---------------------------------------------------------------------------
// Kernel 1 (fused diag + sim):
//   grid = (BATCH/BG, POOL); block = 256 = 8 warps.
//   Each block owns one k and 8 batch rows. Phase 1: cooperatively compute
//   diag[k,:] = sum_l e_p[k,l,:]^2 and stage e_a[k,:] into smem.
//   Phase 2: warp w computes sim[b0+w, k] via a 3-way warp reduction.
// ---------------------------------------------------------------------------
__global__ void sim_fused_kernel(const float* __restrict__ x_querry,
                                 const float* __restrict__ e_a,
                                 const float* __restrict__ e_p,
                                 const int*   __restrict__ task_id_p) {
    const int task_end = (*task_id_p + 1) * (POOL / NTASKS);
    const int k = blockIdx.y;
    if (k >= task_end) return;

    __shared__ float s_diag[EMBD];
    __shared__ float s_ea[EMBD];

    // Phase 1: diag + ea into smem (256 threads over 768 elems)
    const float* epk = e_p + (size_t)k * PLEN * EMBD;
    for (int d = threadIdx.x; d < EMBD; d += 256) {
        float acc = 0.f;
#pragma unroll
        for (int l = 0; l < PLEN; l++) {
            float v = epk[l * EMBD + d];
            acc += v * v;
        }
        s_diag[d] = acc;
        s_ea[d]   = e_a[(size_t)k * EMBD + d];
    }
    __syncthreads();

    // Phase 2: one warp per batch row
    const int warp = threadIdx.x >> 5;
    const int lane = threadIdx.x & 31;
    const int b = blockIdx.x * BG + warp;
    const int row = POOL - task_end + k;

    const float4* xq4 = (const float4*)(x_querry + ((size_t)b * POOL + row) * EMBD);
    const float4* ea4 = (const float4*)s_ea;
    const float4* dg4 = (const float4*)s_diag;

    float s1 = 0.f, s2 = 0.f, s3 = 0.f;
#pragma unroll
    for (int j = 0; j < ED4 / 32; j++) {   // 6 iterations
        int idx = lane + j * 32;
        float4 x = xq4[idx];
        float4 e = ea4[idx];
        float4 g = dg4[idx];
        float a, aa;
        a = x.x * e.x; aa = a * a; s3 += aa; s1 += aa * g.x; s2 += aa * g.x * g.x;
        a = x.y * e.y; aa = a * a; s3 += aa; s1 += aa * g.y; s2 += aa * g.y * g.y;
        a = x.z * e.z; aa = a * a; s3 += aa; s1 += aa * g.z; s2 += aa * g.z * g.z;
        a = x.w * e.w; aa = a * a; s3 += aa; s1 += aa * g.w; s2 += aa * g.w * g.w;
    }
#pragma unroll
    for (int o = 16; o > 0; o >>= 1) {
        s1 += __shfl_down_sync(0xFFFFFFFFu, s1, o);
        s2 += __shfl_down_sync(0xFFFFFFFFu, s2, o);
        s3 += __shfl_down_sync(0xFFFFFFFFu, s3, o);
    }
    if (lane == 0) {
        const float eps = 1e-12f;
        float n1 = fmaxf(sqrtf(s2), eps);
        float n2 = fmaxf(sqrtf(s3), eps);
        g_sim[(size_t)b * POOL + k] = s1 / (n1 * n2);
    }
}

// ---------------------------------------------------------------------------
// Kernel 2 (mega): first PMT_BLOCKS blocks compute the einsum output;
// remaining blocks stream-copy x_block -> out tail with evict-first hints.
// ---------------------------------------------------------------------------
__global__ void mega_kernel(const float* __restrict__ e_p,
                            const float* __restrict__ x_block,
                            const int*   __restrict__ task_id_p,
                            float* __restrict__ out,
                            size_t xb_float4s) {
    if (blockIdx.x < PMT_BLOCKS) {
        // ---- einsum: int_pmt[b,l,d] = sum_k sim[b,k] * e_p[k,l,d] ----
        const int task_end = (*task_id_p + 1) * (POOL / NTASKS);
        const int b = blockIdx.x;

        __shared__ float s_sim[POOL];
        if (threadIdx.x < POOL)
            s_sim[threadIdx.x] = g_sim[(size_t)b * POOL + threadIdx.x];
        __syncthreads();

        const float4* ep4 = (const float4*)e_p;
        const size_t KEY4 = (size_t)BATCH * (PLEN / 2) * ED4;

        // PLEN*ED4 = 1536 float4 outputs per b; 256 threads -> 6 each
        for (int idx = threadIdx.x; idx < PLEN * ED4; idx += 256) {
            int l  = idx / ED4;
            int d4 = idx % ED4;
            float4 acc = make_float4(0.f, 0.f, 0.f, 0.f);
            for (int kk = 0; kk < task_end; kk++) {
                float s  = s_sim[kk];
                float4 v = ep4[((size_t)kk * PLEN + l) * ED4 + d4];
                acc.x += s * v.x; acc.y += s * v.y;
                acc.z += s * v.z; acc.w += s * v.w;
            }
            float4* o4;
            if (l < PLEN / 2)
                o4 = (float4*)out + ((size_t)b * (PLEN / 2) + l) * ED4 + d4;
            else
                o4 = (float4*)out + KEY4 + ((size_t)b * (PLEN / 2) + (l - PLEN / 2)) * ED4 + d4;
            *o4 = acc;
        }
    } else {
        // ---- streaming copy: x_block -> out + BATCH*PLEN*EMBD ----
        const float4* src = (const float4*)x_block;
        float4* dst = (float4*)(out + (size_t)BATCH * PLEN * EMBD);

        const size_t nthreads = (size_t)COPY_BLOCKS * 256;
        size_t tid = (size_t)(blockIdx.x - PMT_BLOCKS) * 256 + threadIdx.x;

        size_t i = tid;
        // 4-way independent unroll for MLP
        for (; i + 3 * nthreads < xb_float4s; i += 4 * nthreads) {
            float4 v0 = __ldcs(src + i);
            float4 v1 = __ldcs(src + i + nthreads);
            float4 v2 = __ldcs(src + i + 2 * nthreads);
            float4 v3 = __ldcs(src + i + 3 * nthreads);
            __stcs(dst + i,                v0);
            __stcs(dst + i + nthreads,     v1);
            __stcs(dst + i + 2 * nthreads, v2);
            __stcs(dst + i + 3 * nthreads, v3);
        }
        for (; i < xb_float4s; i += nthreads)
            __stcs(dst + i, __ldcs(src + i));
    }
}

// ---------------------------------------------------------------------------
// Launch
// Inputs (metadata order): x_querry, x_block, e_a, e_p, idx, task_id
// Output: [int_e_key (512*4*768) | int_e_value (512*4*768) | x_block] fp32
// ---------------------------------------------------------------------------
extern "C" void kernel_launch(void* const* d_in, const int* in_sizes, int n_in,
                              void* d_out, int out_size) {
    const float* x_querry = (const float*)d_in[0];
    const float* x_block  = (const float*)d_in[1];
    const float* e_a      = (const float*)d_in[2];
    const float* e_p      = (const float*)d_in[3];
    const int*   task_id  = (const int*)d_in[5];
    float* out = (float*)d_out;

    // Fused diag+sim
    dim3 sim_grid(BATCH / BG, POOL);
    sim_fused_kernel<<<sim_grid, 256>>>(x_querry, e_a, e_p, task_id);

    // Mega: pmt + streaming copy
    size_t xb_float4s = (size_t)in_sizes[1] / 4;
    mega_kernel<<<PMT_BLOCKS + COPY_BLOCKS, 256>>>(e_p, x_block, task_id, out,
                                                   xb_float4s);
}